// round 6
// baseline (speedup 1.0000x reference)
#include <cuda_runtime.h>
#include <cuda_fp16.h>
#include <math.h>
#include <stdint.h>

// Problem constants
#define Bb 4
#define Ll 4096
#define Hh 1024
#define Nn 16
#define Pc 64           // chunk length
#define NCk 64          // Ll / Pc
#define EPSV 1e-6f

// ---------------- scratch (static device globals; no allocation) ----------------
__device__ float  g_u  [(size_t)Bb*Hh*Ll];   // normalized, masked, (B,H,L)  64MB
__device__ float2 g_lam [Hh*Nn];
__device__ float2 g_lamP[Hh*Nn];
__device__ float2 g_cd2 [Hh*Nn];
__device__ float2 g_Sloc[(size_t)Bb*Hh*NCk*Nn];   // 33.5MB
__device__ float2 g_Sin [(size_t)Bb*Hh*NCk*Nn];   // 33.5MB
__device__ __half g_wf16[2048u*1024u];            // W fp16 [o][k]      4MB
__device__ __half g_yf16[(size_t)1024u*16384u];   // Y fp16 [k=h][n]   32MB

// ================= PTX helpers (legal on base compute_103) =================
__device__ __forceinline__ uint32_t smem_u32(const void* p) {
    uint32_t a;
    asm("{ .reg .u64 t; cvta.to.shared.u64 t, %1; cvt.u32.u64 %0, t; }" : "=r"(a) : "l"(p));
    return a;
}
__device__ __forceinline__ void cp16(uint32_t dst, const void* src) {
    asm volatile("cp.async.cg.shared.global [%0], [%1], 16;" :: "r"(dst), "l"(src));
}
__device__ __forceinline__ void cp_commit() { asm volatile("cp.async.commit_group;"); }
__device__ __forceinline__ void cp_wait2()  { asm volatile("cp.async.wait_group 2;"); }
__device__ __forceinline__ void ldsm4(uint32_t* r, uint32_t addr) {
    asm volatile("ldmatrix.sync.aligned.m8n8.x4.shared.b16 {%0,%1,%2,%3}, [%4];"
                 : "=r"(r[0]), "=r"(r[1]), "=r"(r[2]), "=r"(r[3]) : "r"(addr));
}
__device__ __forceinline__ void ldsm4t(uint32_t* r, uint32_t addr) {
    asm volatile("ldmatrix.sync.aligned.m8n8.x4.trans.shared.b16 {%0,%1,%2,%3}, [%4];"
                 : "=r"(r[0]), "=r"(r[1]), "=r"(r[2]), "=r"(r[3]) : "r"(addr));
}
__device__ __forceinline__ void mma16816(float* d, const uint32_t* a, const uint32_t* b) {
    asm volatile("mma.sync.aligned.m16n8k16.row.col.f32.f16.f16.f32 "
                 "{%0,%1,%2,%3}, {%4,%5,%6,%7}, {%8,%9}, {%0,%1,%2,%3};"
                 : "+f"(d[0]), "+f"(d[1]), "+f"(d[2]), "+f"(d[3])
                 : "r"(a[0]), "r"(a[1]), "r"(a[2]), "r"(a[3]), "r"(b[0]), "r"(b[1]));
}

// ---------------- kernel 0: per-(h,n) constants (double) + W fp32->fp16 ----------------
__global__ void fused_pre_kernel(const float* __restrict__ log_dt,
                                 const float* __restrict__ log_A_real,
                                 const float* __restrict__ A_imag,
                                 const float* __restrict__ C_real,
                                 const float* __restrict__ C_imag,
                                 const float* __restrict__ wmat) {
    unsigned int bid = blockIdx.x;
    if (bid < 8192u) {
        unsigned int i = bid * 256 + threadIdx.x;
        g_wf16[i] = __float2half_rn(wmat[i]);
        return;
    }
    int idx = (int)(bid - 8192u) * 256 + threadIdx.x;
    if (idx >= Hh * Nn) return;
    int h = idx / Nn;
    double dt  = exp((double)log_dt[h]);
    double Are = -exp((double)log_A_real[idx]);
    double Aim = (double)A_imag[idx];
    double dre = Are * dt, dim = Aim * dt;
    double er  = exp(dre);
    double lr  = er * cos(dim), li = er * sin(dim);
    g_lam[idx] = make_float2((float)lr, (float)li);
    double erp = exp(dre * (double)Pc);
    g_lamP[idx] = make_float2((float)(erp * cos(dim * (double)Pc)),
                              (float)(erp * sin(dim * (double)Pc)));
    double e1r = lr - 1.0, e1i = li;
    double Cr = (double)C_real[idx], Ci = (double)C_imag[idx];
    double nr = Cr * e1r - Ci * e1i;
    double ni = Cr * e1i + Ci * e1r;
    double den = Are * Are + Aim * Aim;
    double cdr = (nr * Are + ni * Aim) / den;
    double cdi = (ni * Are - nr * Aim) / den;
    g_cd2[idx] = make_float2((float)(2.0 * cdr), (float)(2.0 * cdi));
}

// ---------------- kernel 1: fused RMSNorm + mask + transpose ----------------
// Block: (b, 32 l-rows). smem tile [32][1025] fp32 + rm[32] + w[1024].
#define NF_TILE  (32 * 1025)
#define NF_SMEM  ((NF_TILE + 32 + 1024) * 4)
__global__ __launch_bounds__(256) void norm_fused_kernel(const float* __restrict__ hs,
                                                         const float* __restrict__ mask,
                                                         const float* __restrict__ w) {
    extern __shared__ float sm[];
    float* tile = sm;
    float* rm   = sm + NF_TILE;
    float* w_s  = sm + NF_TILE + 32;
    int b  = blockIdx.y;
    int l0 = blockIdx.x * 32;
    int tid = threadIdx.x;
    int row = tid >> 3;       // 0..31
    int sub = tid & 7;        // 0..7

    for (int i = tid; i < 1024; i += 256) w_s[i] = w[i];

    const float4* src = (const float4*)(hs + ((size_t)(b * Ll + l0 + row)) * Hh);
    float ss = 0.f;
#pragma unroll
    for (int i = 0; i < 32; i++) {
        int col4 = i * 8 + sub;                 // conflict-free interleave
        float4 v = src[col4];
        ss += v.x * v.x + v.y * v.y + v.z * v.z + v.w * v.w;
        float* dst = &tile[row * 1025 + col4 * 4];   // stride 1025: scalar stores (alignment!)
        dst[0] = v.x; dst[1] = v.y; dst[2] = v.z; dst[3] = v.w;
    }
#pragma unroll
    for (int o = 4; o; o >>= 1) ss += __shfl_xor_sync(0xffffffffu, ss, o);
    if (sub == 0)
        rm[row] = rsqrtf(ss * (1.0f / Hh) + EPSV) * mask[b * Ll + l0 + row];
    __syncthreads();

#pragma unroll 8
    for (int i = 0; i < 128; i++) {
        int lin = i * 256 + tid;
        int h = lin >> 5, l = lin & 31;
        g_u[((size_t)(b * Hh + h)) * Ll + l0 + l] = tile[l * 1025 + h] * rm[l] * w_s[h];
    }
}

// ---------------- kernel 3: per-chunk local end-states (Pc=64, 2 warps/(b,h)) -------
__global__ void scan_local_kernel() {
    int gt = blockIdx.x * blockDim.x + threadIdx.x;
    int w  = gt >> 5;
    int lane = gt & 31;
    int bh = w >> 1;
    int c  = ((w & 1) << 5) | lane;
    int hh = bh & (Hh - 1);
    float lr[Nn], li[Nn], sr[Nn], si[Nn];
#pragma unroll
    for (int n = 0; n < Nn; n++) {
        float2 v = g_lam[hh * Nn + n];
        lr[n] = v.x; li[n] = v.y; sr[n] = 0.f; si[n] = 0.f;
    }
    const float4* up = (const float4*)(g_u + (size_t)bh * Ll + c * Pc);
#pragma unroll 2
    for (int q = 0; q < Pc / 4; q++) {
        float4 uv = up[q];
        float xs[4] = {uv.x, uv.y, uv.z, uv.w};
#pragma unroll
        for (int e = 0; e < 4; e++) {
            float x = xs[e];
#pragma unroll
            for (int n = 0; n < Nn; n++) {
                float nr = fmaf(lr[n], sr[n], fmaf(-li[n], si[n], x));
                float ni = fmaf(lr[n], si[n], li[n] * sr[n]);
                sr[n] = nr; si[n] = ni;
            }
        }
    }
    float2* outp = g_Sloc + ((size_t)bh * NCk + c) * Nn;
#pragma unroll
    for (int n = 0; n < Nn; n++) outp[n] = make_float2(sr[n], si[n]);
}

// ---------------- kernel 4: inter-chunk combine ----------------
__global__ void scan_combine_kernel() {
    int t = blockIdx.x * blockDim.x + threadIdx.x;
    if (t >= Bb * Hh * Nn) return;
    int n  = t & (Nn - 1);
    int bh = t >> 4;
    int hh = bh & (Hh - 1);
    float2 lp = g_lamP[hh * Nn + n];
    float sre = 0.f, sim = 0.f;
#pragma unroll
    for (int c = 0; c < NCk; c++) {
        size_t idx = ((size_t)bh * NCk + c) * Nn + n;
        g_Sin[idx] = make_float2(sre, sim);
        float2 sl = g_Sloc[idx];
        float nr = fmaf(lp.x, sre, fmaf(-lp.y, sim, sl.x));
        float ni = fmaf(lp.x, sim, fmaf(lp.y, sre, sl.y));
        sre = nr; sim = ni;
    }
}

// ---------------- kernel 5: output scan + D skip + exact GELU -> fp16 [h][n] -------
__global__ void scan_out_kernel(const float* __restrict__ Dvec) {
    int gt = blockIdx.x * blockDim.x + threadIdx.x;
    int w  = gt >> 5;
    int lane = gt & 31;
    int bh = w >> 1;
    int c  = ((w & 1) << 5) | lane;
    int hh = bh & (Hh - 1);
    int b  = bh >> 10;
    float lr[Nn], li[Nn], cr[Nn], ci[Nn], sr[Nn], si[Nn];
#pragma unroll
    for (int n = 0; n < Nn; n++) {
        float2 v = g_lam[hh * Nn + n];  lr[n] = v.x; li[n] = v.y;
        float2 cc = g_cd2[hh * Nn + n]; cr[n] = cc.x; ci[n] = cc.y;
        float2 s0 = g_Sin[((size_t)bh * NCk + c) * Nn + n];
        sr[n] = s0.x; si[n] = s0.y;
    }
    float Dh = Dvec[hh];
    const float4* up = (const float4*)(g_u + (size_t)bh * Ll + c * Pc);
    uint2* yp = (uint2*)(g_yf16 + (size_t)hh * 16384 + (size_t)b * 4096 + c * Pc);
#pragma unroll 2
    for (int q = 0; q < Pc / 4; q++) {
        float4 uv = up[q];
        float xs[4] = {uv.x, uv.y, uv.z, uv.w};
        float ys[4];
#pragma unroll
        for (int e = 0; e < 4; e++) {
            float x = xs[e];
            float y = Dh * x;
#pragma unroll
            for (int n = 0; n < Nn; n++) {
                float nr = fmaf(lr[n], sr[n], fmaf(-li[n], si[n], x));
                float ni = fmaf(lr[n], si[n], li[n] * sr[n]);
                sr[n] = nr; si[n] = ni;
                y = fmaf(cr[n], nr, y);
                y = fmaf(-ci[n], ni, y);
            }
            ys[e] = 0.5f * y * (1.0f + erff(y * 0.70710678118654752f));
        }
        __half2 h2a = __floats2half2_rn(ys[0], ys[1]);
        __half2 h2b = __floats2half2_rn(ys[2], ys[3]);
        uint2 pk;
        pk.x = *(uint32_t*)&h2a;
        pk.y = *(uint32_t*)&h2b;
        yp[q] = pk;
    }
}

// ---------------- kernel 6: fp16 1-pass GEMM + GLU + residual ----------------
// CTA tile: M=128 (64 a-rows + 64 gate-rows), N=256, K-chunk 32, 512 threads.
#define KC 32
#define ROWA 80                          // 64B data + 16 pad
#define ROWB2 528                        // 512B data + 16 pad
#define A_REG (128*ROWA)                 // 10240
#define B_REG (KC*ROWB2)                 // 16896
#define STG (A_REG + B_REG)              // 27136
#define NSTG 4
#define GSMEM (NSTG*STG)                 // 108544

__device__ __forceinline__ void load_stage(uint32_t sbase, int s, int chunk, int by, int bx) {
    int tid = threadIdx.x;
    uint32_t stb = sbase + s * STG;
    // A: 128 rows x 64B  (512 cp16)
    {
        int row = tid >> 2, seg = tid & 3;
        int wrow = (row < 64) ? (by * 64 + row) : (1024 + by * 64 + row - 64);
        cp16(stb + (unsigned)row * ROWA + seg * 16,
             g_wf16 + (size_t)wrow * 1024 + chunk * KC + seg * 8);
    }
    // B: 32 rows x 512B  (1024 cp16)
#pragma unroll
    for (int i = 0; i < 2; i++) {
        int t = i * 512 + tid;
        int row = t >> 5, seg = t & 31;
        cp16(stb + A_REG + (unsigned)row * ROWB2 + seg * 16,
             g_yf16 + (size_t)(chunk * KC + row) * 16384 + bx * 256 + seg * 8);
    }
}

__global__ __launch_bounds__(512, 1) void gemm_glu_kernel(const float* __restrict__ bias,
                                                          const float* __restrict__ hs,
                                                          float* __restrict__ out) {
    extern __shared__ char smem[];
    uint32_t sbase = smem_u32(smem);
    int tid  = threadIdx.x;
    int wid  = tid >> 5;
    int lane = tid & 31;
    int by = blockIdx.x;   // o-tile (64 outputs); fast -> CTAs sharing B co-resident
    int bx = blockIdx.y;   // n-tile (256 cols)

    int wm = (wid & 1) * 64;        // 2 warps along m
    int wn = (wid >> 1) * 32;       // 8 warps along n (0..224)
    uint32_t aOff = (uint32_t)(wm + (lane & 15)) * ROWA + (uint32_t)(lane >> 4) * 16;
    uint32_t bOff = (uint32_t)(lane & 15) * ROWB2 + (uint32_t)(lane >> 4) * 16
                  + (uint32_t)wn * 2;

    float acc[64];
#pragma unroll
    for (int i = 0; i < 64; i++) acc[i] = 0.f;

#pragma unroll
    for (int p = 0; p < 3; p++) { load_stage(sbase, p, p, by, bx); cp_commit(); }

    for (int c = 0; c < 32; c++) {
        int s = c & 3;
        cp_wait2();
        __syncthreads();
        if (c + 3 < 32) load_stage(sbase, (c + 3) & 3, c + 3, by, bx);
        cp_commit();
        uint32_t ab = sbase + s * STG;
        uint32_t bb = ab + A_REG;
#pragma unroll
        for (int ks = 0; ks < 2; ks++) {
            uint32_t bf[8], af[16];
            ldsm4t(&bf[0], bb + bOff + (unsigned)ks * (16 * ROWB2));
            ldsm4t(&bf[4], bb + bOff + (unsigned)ks * (16 * ROWB2) + 32);
#pragma unroll
            for (int i = 0; i < 4; i++)
                ldsm4(&af[i * 4], ab + aOff + (unsigned)i * (16 * ROWA) + ks * 32);
#pragma unroll
            for (int i = 0; i < 4; i++)
#pragma unroll
                for (int j = 0; j < 4; j++)
                    mma16816(&acc[(i * 4 + j) * 4], &af[i * 4], &bf[j * 2]);
        }
    }

    // epilogue: two 128-col rounds through smem [128 n][132 floats]
    float* zsm = (float*)smem;
    int qr = lane >> 2, t4 = lane & 3;
    int n0 = bx * 256, o0 = by * 64;
#pragma unroll
    for (int r = 0; r < 2; r++) {
        __syncthreads();
        if ((wn >> 7) == r) {
            int wnl = wn & 127;
#pragma unroll
            for (int i = 0; i < 4; i++)
#pragma unroll
                for (int j = 0; j < 4; j++) {
                    int m = wm + i * 16 + qr;
                    int n = wnl + j * 8 + t4 * 2;
                    const float* p = &acc[(i * 4 + j) * 4];
                    zsm[n * 132 + m]           = p[0];
                    zsm[(n + 1) * 132 + m]     = p[1];
                    zsm[n * 132 + m + 8]       = p[2];
                    zsm[(n + 1) * 132 + m + 8] = p[3];
                }
        }
        __syncthreads();
#pragma unroll
        for (int it = 0; it < 4; it++) {
            int task = it * 512 + tid;
            int nrow = task >> 4, mg = (task & 15) * 4;
            float4 za = *(const float4*)&zsm[nrow * 132 + mg];
            float4 zg = *(const float4*)&zsm[nrow * 132 + 64 + mg];
            float4 ba = *(const float4*)(bias + o0 + mg);
            float4 bg = *(const float4*)(bias + 1024 + o0 + mg);
            size_t addr = (size_t)(n0 + r * 128 + nrow) * 1024 + o0 + mg;
            float4 hv = *(const float4*)(hs + addr);
            float4 ov;
            ov.x = hv.x + (za.x + ba.x) * (1.0f / (1.0f + expf(-(zg.x + bg.x))));
            ov.y = hv.y + (za.y + ba.y) * (1.0f / (1.0f + expf(-(zg.y + bg.y))));
            ov.z = hv.z + (za.z + ba.z) * (1.0f / (1.0f + expf(-(zg.z + bg.z))));
            ov.w = hv.w + (za.w + ba.w) * (1.0f / (1.0f + expf(-(zg.w + bg.w))));
            *(float4*)(out + addr) = ov;
        }
    }
}

// ---------------- launch ----------------
extern "C" void kernel_launch(void* const* d_in, const int* in_sizes, int n_in,
                              void* d_out, int out_size) {
    const float* hidden     = (const float*)d_in[0];
    const float* attn_mask  = (const float*)d_in[1];
    const float* norm_w     = (const float*)d_in[2];
    const float* log_dt     = (const float*)d_in[3];
    const float* log_A_real = (const float*)d_in[4];
    const float* A_imag     = (const float*)d_in[5];
    const float* C_real     = (const float*)d_in[6];
    const float* C_imag     = (const float*)d_in[7];
    const float* Dvec       = (const float*)d_in[8];
    const float* out_w      = (const float*)d_in[9];
    const float* out_b      = (const float*)d_in[10];
    float* out = (float*)d_out;

    cudaFuncSetAttribute(gemm_glu_kernel, cudaFuncAttributeMaxDynamicSharedMemorySize, GSMEM);
    cudaFuncSetAttribute(norm_fused_kernel, cudaFuncAttributeMaxDynamicSharedMemorySize, NF_SMEM);

    fused_pre_kernel<<<8192 + 64, 256>>>(log_dt, log_A_real, A_imag, C_real, C_imag, out_w);
    norm_fused_kernel<<<dim3(Ll / 32, Bb), 256, NF_SMEM>>>(hidden, attn_mask, norm_w);
    scan_local_kernel<<<(Bb * Hh * 2 * 32) / 256, 256>>>();
    scan_combine_kernel<<<(Bb * Hh * Nn) / 256, 256>>>();
    scan_out_kernel<<<(Bb * Hh * 2 * 32) / 256, 256>>>(Dvec);
    gemm_glu_kernel<<<dim3(16, 64), 512, GSMEM>>>(out_b, hidden, out);
}